// round 6
// baseline (speedup 1.0000x reference)
#include <cuda_runtime.h>
#include <math_constants.h>

#define BATCH  4
#define NPTS   4096
#define NQ     (BATCH * NPTS)   // 16384
#define CIN    64
#define KNN    16
#define C2     128
#define EPSBN  1e-5f

// ---------------- scratch (no device allocations allowed) ----------------
__device__ float4 g_pack[NQ];          // {x, y, z, |x|^2}
__device__ int    g_idx[NQ * KNN];     // global neighbor indices
__device__ float  g_P0[NQ * 64];       // W0_pts' . points[j]  (folded, no bias)

// ---------------- helpers ----------------
__device__ __forceinline__ float fold_scale(float g, float rv) {
    float v = rv + EPSBN;
    float r = rsqrtf(v);
    r = r * (1.5f - 0.5f * v * r * r);   // one Newton step -> ~1ulp
    return g * r;
}

// replicate reference rounding: (sq_i + sq_j) + (-2*dot), dot as fma chain
__device__ __forceinline__ float dist2f(float qx, float qy, float qz, float qsq, float4 p) {
    float dot = fmaf(qz, p.z, fmaf(qy, p.y, __fmul_rn(qx, p.x)));
    return __fadd_rn(__fadd_rn(qsq, p.w), __fmul_rn(-2.0f, dot));
}

// ---------------- kernel 1: pack xyz + squared norm ----------------
__global__ void pack_kernel(const float* __restrict__ xyz) {
    int i = blockIdx.x * blockDim.x + threadIdx.x;
    if (i < NQ) {
        float x = xyz[3 * i + 0];
        float y = xyz[3 * i + 1];
        float z = xyz[3 * i + 2];
        float sq = fmaf(z, z, fmaf(y, y, __fmul_rn(x, x)));
        g_pack[i] = make_float4(x, y, z, sq);
    }
}

// ---------------- kernel 2: P0[j][o] = sum_c W0'[o][3+c] * points[j][c] ----------------
__global__ void __launch_bounds__(256) p0_kernel(const float* __restrict__ points,
                                                 const float* __restrict__ w0,
                                                 const float* __restrict__ g0,
                                                 const float* __restrict__ rv0) {
    __shared__ float w0f[64][64];   // [c][o], folded
    int tid = threadIdx.x;
    for (int e = tid; e < 4096; e += 256) {
        int o = e & 63, c = e >> 6;
        float s = fold_scale(g0[o], rv0[o]);
        w0f[c][o] = w0[o * 67 + 3 + c] * s;
    }
    __syncthreads();

    int o     = tid & 63;
    int jl    = tid >> 6;               // 0..3
    int jbase = blockIdx.x * 64;
#pragma unroll 1
    for (int t = 0; t < 16; t++) {
        int j = jbase + jl + (t << 2);
        const float4* prow = (const float4*)(points + (size_t)j * 64);
        float acc = 0.0f;
#pragma unroll
        for (int c4 = 0; c4 < 16; c4++) {
            float4 p = prow[c4];
            acc = fmaf(p.x, w0f[c4 * 4 + 0][o], acc);
            acc = fmaf(p.y, w0f[c4 * 4 + 1][o], acc);
            acc = fmaf(p.z, w0f[c4 * 4 + 2][o], acc);
            acc = fmaf(p.w, w0f[c4 * 4 + 3][o], acc);
        }
        g_P0[(size_t)j * 64 + o] = acc;
    }
}

// ---------------- kernel 3: exact KNN, lane-per-query ----------------
__device__ __forceinline__ void knn_insert(float dd, int c, float* d, int* id, float& wmax) {
    bool done = false;
#pragma unroll
    for (int i = 0; i < KNN; i++) {
        bool m = (!done) && (d[i] == wmax);
        if (m) { d[i] = dd; id[i] = c; }
        done = done || m;
    }
    wmax = d[0];
#pragma unroll
    for (int i = 1; i < KNN; i++) wmax = fmaxf(wmax, d[i]);
}

__global__ void __launch_bounds__(128) knn_kernel() {
    int q = blockIdx.x * 128 + threadIdx.x;   // 4096 % 128 == 0 -> block within one batch
    int base = (q >> 12) << 12;
    const float4* __restrict__ cand = g_pack + base;

    float4 me = g_pack[q];
    float qx = me.x, qy = me.y, qz = me.z, qsq = me.w;

    float d[KNN];
    int   id[KNN];
#pragma unroll
    for (int i = 0; i < KNN; i++) { d[i] = CUDART_INF_F; id[i] = 0; }
    float wmax = CUDART_INF_F;

    for (int c = 0; c < NPTS; c += 4) {
        float4 p0 = cand[c + 0];
        float4 p1 = cand[c + 1];
        float4 p2 = cand[c + 2];
        float4 p3 = cand[c + 3];
        float dd0 = dist2f(qx, qy, qz, qsq, p0);
        float dd1 = dist2f(qx, qy, qz, qsq, p1);
        float dd2 = dist2f(qx, qy, qz, qsq, p2);
        float dd3 = dist2f(qx, qy, qz, qsq, p3);
        if (dd0 < wmax) knn_insert(dd0, base + c + 0, d, id, wmax);
        if (dd1 < wmax) knn_insert(dd1, base + c + 1, d, id, wmax);
        if (dd2 < wmax) knn_insert(dd2, base + c + 2, d, id, wmax);
        if (dd3 < wmax) knn_insert(dd3, base + c + 3, d, id, wmax);
    }

#pragma unroll
    for (int i = 0; i < KNN; i++) g_idx[(size_t)q * KNN + i] = id[i];
}

// ---------------- kernel 4: fused MLP + maxpool ----------------
// 128 threads = 8 queries x 16 neighbors. Dynamic smem layout (floats):
//   [0)      W1S  4096   (o*64+c, folded)
//   [4096)   W2S  8192   (o*64+c, folded)
//   [12288)  W0B  256    (64 x float4 {wx,wy,wz,b0'})
//   [12544)  B1F  64
//   [12608)  B2F  128
//   [12736)  S1   64
//   [12800)  S2   128
#define MLP_SMEM_FLOATS 12928
#define MLP_SMEM_BYTES  (MLP_SMEM_FLOATS * 4)

__global__ void __launch_bounds__(128) mlp_kernel(
    const float* __restrict__ w0, const float* __restrict__ b0, const float* __restrict__ g0,
    const float* __restrict__ be0, const float* __restrict__ rm0, const float* __restrict__ rv0,
    const float* __restrict__ w1, const float* __restrict__ b1, const float* __restrict__ g1,
    const float* __restrict__ be1, const float* __restrict__ rm1, const float* __restrict__ rv1,
    const float* __restrict__ w2, const float* __restrict__ b2, const float* __restrict__ g2,
    const float* __restrict__ be2, const float* __restrict__ rm2, const float* __restrict__ rv2,
    float* __restrict__ out)
{
    extern __shared__ float sm[];
    float*  W1S = sm;
    float*  W2S = sm + 4096;
    float4* W0B = (float4*)(sm + 12288);
    float*  B1F = sm + 12544;
    float*  B2F = sm + 12608;
    float*  S1  = sm + 12736;
    float*  S2  = sm + 12800;

    int tid = threadIdx.x;

    // ---- fold BN into scales/biases ----
    if (tid < 64) {
        float s0  = fold_scale(g0[tid], rv0[tid]);
        float b0f = (b0[tid] - rm0[tid]) * s0 + be0[tid];
        W0B[tid] = make_float4(w0[tid * 67 + 0] * s0,
                               w0[tid * 67 + 1] * s0,
                               w0[tid * 67 + 2] * s0, b0f);
        float s1v = fold_scale(g1[tid], rv1[tid]);
        S1[tid]  = s1v;
        B1F[tid] = (b1[tid] - rm1[tid]) * s1v + be1[tid];
    }
    {
        float s2v = fold_scale(g2[tid], rv2[tid]);
        S2[tid]  = s2v;
        B2F[tid] = (b2[tid] - rm2[tid]) * s2v + be2[tid];
    }
    __syncthreads();

    for (int e = tid; e < 4096; e += 128) W1S[e] = w1[e] * S1[e >> 6];
    for (int e = tid; e < 8192; e += 128) W2S[e] = w2[e] * S2[e >> 6];
    __syncthreads();

    // ---- row work: thread = one (query, neighbor) pair ----
    int q = blockIdx.x * 8 + (tid >> 4);
    int j = g_idx[((size_t)q << 4) + (tid & 15)];

    float4 pj = g_pack[j];
    float4 pq = g_pack[q];
    float rx = pj.x - pq.x, ry = pj.y - pq.y, rz = pj.z - pq.z;

    // layer 0: h0 = relu(P0[j] + W0x . rel + b0')
    float h0[64];
    const float4* p0row = (const float4*)(g_P0 + (size_t)j * 64);
#pragma unroll
    for (int o4 = 0; o4 < 16; o4++) {
        float4 p = p0row[o4];
        float pv[4] = { p.x, p.y, p.z, p.w };
#pragma unroll
        for (int u = 0; u < 4; u++) {
            int o = o4 * 4 + u;
            float4 w = W0B[o];
            float v = fmaf(w.x, rx, fmaf(w.y, ry, fmaf(w.z, rz, pv[u] + w.w)));
            h0[o] = fmaxf(v, 0.0f);
        }
    }

    // layer 1: h1 = relu(W1' . h0 + b1')
    float h1[64];
#pragma unroll 2
    for (int o = 0; o < 64; o++) {
        const float4* wr = (const float4*)(W1S + o * 64);
        float acc = B1F[o];
#pragma unroll
        for (int c4 = 0; c4 < 16; c4++) {
            float4 a = wr[c4];
            acc = fmaf(a.x, h0[c4 * 4 + 0], acc);
            acc = fmaf(a.y, h0[c4 * 4 + 1], acc);
            acc = fmaf(a.z, h0[c4 * 4 + 2], acc);
            acc = fmaf(a.w, h0[c4 * 4 + 3], acc);
        }
        h1[o] = fmaxf(acc, 0.0f);
    }

    // layer 2 + maxpool over 16 neighbors (lanes 0-15 / 16-31 = one query each)
    int lane = tid & 31;
    float* orow = out + (size_t)q * C2;
#pragma unroll 2
    for (int o = 0; o < C2; o++) {
        const float4* wr = (const float4*)(W2S + o * 64);
        float acc = B2F[o];
#pragma unroll
        for (int c4 = 0; c4 < 16; c4++) {
            float4 a = wr[c4];
            acc = fmaf(a.x, h1[c4 * 4 + 0], acc);
            acc = fmaf(a.y, h1[c4 * 4 + 1], acc);
            acc = fmaf(a.z, h1[c4 * 4 + 2], acc);
            acc = fmaf(a.w, h1[c4 * 4 + 3], acc);
        }
        float v = fmaxf(acc, 0.0f);
        v = fmaxf(v, __shfl_xor_sync(0xFFFFFFFFu, v, 1));
        v = fmaxf(v, __shfl_xor_sync(0xFFFFFFFFu, v, 2));
        v = fmaxf(v, __shfl_xor_sync(0xFFFFFFFFu, v, 4));
        v = fmaxf(v, __shfl_xor_sync(0xFFFFFFFFu, v, 8));
        if ((lane & 15) == 0) orow[o] = v;
    }
}

// ---------------- launch ----------------
extern "C" void kernel_launch(void* const* d_in, const int* in_sizes, int n_in,
                              void* d_out, int out_size) {
    (void)in_sizes; (void)n_in; (void)out_size;
    const float* xyz    = (const float*)d_in[0];
    const float* points = (const float*)d_in[1];
    const float* w0  = (const float*)d_in[2];
    const float* b0  = (const float*)d_in[3];
    const float* g0  = (const float*)d_in[4];
    const float* be0 = (const float*)d_in[5];
    const float* rm0 = (const float*)d_in[6];
    const float* rv0 = (const float*)d_in[7];
    const float* w1  = (const float*)d_in[8];
    const float* b1  = (const float*)d_in[9];
    const float* g1  = (const float*)d_in[10];
    const float* be1 = (const float*)d_in[11];
    const float* rm1 = (const float*)d_in[12];
    const float* rv1 = (const float*)d_in[13];
    const float* w2  = (const float*)d_in[14];
    const float* b2  = (const float*)d_in[15];
    const float* g2  = (const float*)d_in[16];
    const float* be2 = (const float*)d_in[17];
    const float* rm2 = (const float*)d_in[18];
    const float* rv2 = (const float*)d_in[19];
    float* out = (float*)d_out;

    cudaFuncSetAttribute(mlp_kernel, cudaFuncAttributeMaxDynamicSharedMemorySize,
                         MLP_SMEM_BYTES);

    pack_kernel<<<NQ / 256, 256>>>(xyz);
    p0_kernel<<<NQ / 64, 256>>>(points, w0, g0, rv0);
    knn_kernel<<<NQ / 128, 128>>>();
    mlp_kernel<<<NQ / 8, 128, MLP_SMEM_BYTES>>>(
        w0, b0, g0, be0, rm0, rv0,
        w1, b1, g1, be1, rm1, rv1,
        w2, b2, g2, be2, rm2, rv2, out);
}

// round 7
// speedup vs baseline: 1.0117x; 1.0117x over previous
#include <cuda_runtime.h>
#include <math_constants.h>

#define BATCH  4
#define NPTS   4096
#define NQ     (BATCH * NPTS)   // 16384
#define KNN    16
#define NROWS  (NQ * KNN)       // 262144
#define C2     128
#define NSLICE 8
#define SLICEN (NPTS / NSLICE)  // 512
#define EPSBN  1e-5f

// ---------------- scratch (no device allocations allowed) ----------------
__device__ float4 g_pack[NQ];                  // {x, y, z, |x|^2}
__device__ int    g_idx[NROWS];                // [q][k] neighbor indices
__device__ float  g_P0[NQ * 64];               // W0_pts' . points[j]
__device__ float  g_sd[NSLICE * KNN * NQ];     // slice top-16 distances, [slot][q]
__device__ int    g_si[NSLICE * KNN * NQ];     // slice top-16 indices,   [slot][q]
__device__ float  g_H1[(size_t)NROWS * 64];    // relu'd layer-1 activations

// ---------------- helpers ----------------
__device__ __forceinline__ float fold_scale(float g, float rv) {
    float v = rv + EPSBN;
    float r = rsqrtf(v);
    r = r * (1.5f - 0.5f * v * r * r);   // Newton step -> ~1ulp
    return g * r;
}

// replicate reference rounding: (sq_i + sq_j) + (-2*dot), dot as fma chain
__device__ __forceinline__ float dist2f(float qx, float qy, float qz, float qsq, float4 p) {
    float dot = fmaf(qz, p.z, fmaf(qy, p.y, __fmul_rn(qx, p.x)));
    return __fadd_rn(__fadd_rn(qsq, p.w), __fmul_rn(-2.0f, dot));
}

__device__ __forceinline__ void knn_insert(float dd, int c, float* d, int* id, float& wmax) {
    bool done = false;
#pragma unroll
    for (int i = 0; i < KNN; i++) {
        bool m = (!done) && (d[i] == wmax);
        if (m) { d[i] = dd; id[i] = c; }
        done = done || m;
    }
    wmax = d[0];
#pragma unroll
    for (int i = 1; i < KNN; i++) wmax = fmaxf(wmax, d[i]);
}

// ---------------- kernel 1: pack xyz + squared norm ----------------
__global__ void pack_kernel(const float* __restrict__ xyz) {
    int i = blockIdx.x * blockDim.x + threadIdx.x;
    if (i < NQ) {
        float x = xyz[3 * i + 0];
        float y = xyz[3 * i + 1];
        float z = xyz[3 * i + 2];
        float sq = fmaf(z, z, fmaf(y, y, __fmul_rn(x, x)));
        g_pack[i] = make_float4(x, y, z, sq);
    }
}

// ---------------- kernel 2: P0[j][o] = sum_c W0'[o][3+c] * points[j][c] ----------------
__global__ void __launch_bounds__(256) p0_kernel(const float* __restrict__ points,
                                                 const float* __restrict__ w0,
                                                 const float* __restrict__ g0,
                                                 const float* __restrict__ rv0) {
    __shared__ float w0f[64][64];   // [c][o], folded
    int tid = threadIdx.x;
    for (int e = tid; e < 4096; e += 256) {
        int o = e & 63, c = e >> 6;
        float s = fold_scale(g0[o], rv0[o]);
        w0f[c][o] = w0[o * 67 + 3 + c] * s;
    }
    __syncthreads();

    int o     = tid & 63;
    int jl    = tid >> 6;               // 0..3
    int jbase = blockIdx.x * 64;
#pragma unroll 1
    for (int t = 0; t < 16; t++) {
        int j = jbase + jl + (t << 2);
        const float4* prow = (const float4*)(points + (size_t)j * 64);
        float acc = 0.0f;
#pragma unroll
        for (int c4 = 0; c4 < 16; c4++) {
            float4 p = prow[c4];
            acc = fmaf(p.x, w0f[c4 * 4 + 0][o], acc);
            acc = fmaf(p.y, w0f[c4 * 4 + 1][o], acc);
            acc = fmaf(p.z, w0f[c4 * 4 + 2][o], acc);
            acc = fmaf(p.w, w0f[c4 * 4 + 3][o], acc);
        }
        g_P0[(size_t)j * 64 + o] = acc;
    }
}

// ---------------- kernel 3a: per-slice exact top-16 (8 slices per query) --------
// grid (NQ/128, NSLICE), block 128. Thread (q, s) scans candidates
// [512s, 512(s+1)) of q's batch and keeps its exact top-16.
__global__ void __launch_bounds__(128) knnA_kernel() {
    int q = blockIdx.x * 128 + threadIdx.x;   // 128 | 4096 -> whole block same batch
    int s = blockIdx.y;
    int base  = (q >> 12) << 12;
    int cbase = base + (s << 9);
    const float4* __restrict__ cand = g_pack + cbase;

    float4 me = g_pack[q];
    float qx = me.x, qy = me.y, qz = me.z, qsq = me.w;

    float d[KNN];
    int   id[KNN];
#pragma unroll
    for (int i = 0; i < KNN; i++) { d[i] = CUDART_INF_F; id[i] = 0; }
    float wmax = CUDART_INF_F;

    for (int c = 0; c < SLICEN; c += 4) {
        float4 p0 = cand[c + 0];
        float4 p1 = cand[c + 1];
        float4 p2 = cand[c + 2];
        float4 p3 = cand[c + 3];
        float dd0 = dist2f(qx, qy, qz, qsq, p0);
        float dd1 = dist2f(qx, qy, qz, qsq, p1);
        float dd2 = dist2f(qx, qy, qz, qsq, p2);
        float dd3 = dist2f(qx, qy, qz, qsq, p3);
        if (dd0 < wmax) knn_insert(dd0, cbase + c + 0, d, id, wmax);
        if (dd1 < wmax) knn_insert(dd1, cbase + c + 1, d, id, wmax);
        if (dd2 < wmax) knn_insert(dd2, cbase + c + 2, d, id, wmax);
        if (dd3 < wmax) knn_insert(dd3, cbase + c + 3, d, id, wmax);
    }

#pragma unroll
    for (int i = 0; i < KNN; i++) {
        int slot = s * KNN + i;
        g_sd[(size_t)slot * NQ + q] = d[i];
        g_si[(size_t)slot * NQ + q] = id[i];
    }
}

// ---------------- kernel 3b: merge 8x16 slice survivors -> exact top-16 ---------
__global__ void __launch_bounds__(128) knnB_kernel() {
    int q = blockIdx.x * 128 + threadIdx.x;

    float d[KNN];
    int   id[KNN];
#pragma unroll
    for (int i = 0; i < KNN; i++) { d[i] = CUDART_INF_F; id[i] = 0; }
    float wmax = CUDART_INF_F;

#pragma unroll 4
    for (int slot = 0; slot < NSLICE * KNN; slot++) {
        float dd = g_sd[(size_t)slot * NQ + q];
        int   c  = g_si[(size_t)slot * NQ + q];
        if (dd < wmax) knn_insert(dd, c, d, id, wmax);
    }

#pragma unroll
    for (int i = 0; i < KNN; i++) g_idx[(size_t)q * KNN + i] = id[i];
}

// ---------------- kernel 4a: layer0 + layer1 -> g_H1 (streamed, no h1 regs) -----
__global__ void __launch_bounds__(128) mlp1_kernel(
    const float* __restrict__ w0, const float* __restrict__ b0,
    const float* __restrict__ g0, const float* __restrict__ be0,
    const float* __restrict__ rm0, const float* __restrict__ rv0,
    const float* __restrict__ w1, const float* __restrict__ b1,
    const float* __restrict__ g1, const float* __restrict__ be1,
    const float* __restrict__ rm1, const float* __restrict__ rv1)
{
    __shared__ float4 W0B[64];     // {wx, wy, wz, b0'}
    __shared__ float  W1S[4096];   // [o][c] folded
    __shared__ float  B1F[64];
    __shared__ float  S1[64];

    int tid = threadIdx.x;
    if (tid < 64) {
        float s0 = fold_scale(g0[tid], rv0[tid]);
        W0B[tid] = make_float4(w0[tid * 67 + 0] * s0,
                               w0[tid * 67 + 1] * s0,
                               w0[tid * 67 + 2] * s0,
                               (b0[tid] - rm0[tid]) * s0 + be0[tid]);
        float s1v = fold_scale(g1[tid], rv1[tid]);
        S1[tid]  = s1v;
        B1F[tid] = (b1[tid] - rm1[tid]) * s1v + be1[tid];
    }
    __syncthreads();
    for (int e = tid; e < 4096; e += 128) W1S[e] = w1[e] * S1[e >> 6];
    __syncthreads();

    int row = blockIdx.x * 128 + tid;
    int q   = row >> 4;
    int j   = g_idx[row];

    float4 pj = g_pack[j];
    float4 pq = g_pack[q];
    float rx = pj.x - pq.x, ry = pj.y - pq.y, rz = pj.z - pq.z;

    // layer 0
    float h0[64];
    const float4* p0row = (const float4*)(g_P0 + (size_t)j * 64);
#pragma unroll
    for (int o4 = 0; o4 < 16; o4++) {
        float4 p = p0row[o4];
        float pv[4] = { p.x, p.y, p.z, p.w };
#pragma unroll
        for (int u = 0; u < 4; u++) {
            int o = o4 * 4 + u;
            float4 w = W0B[o];
            float v = fmaf(w.x, rx, fmaf(w.y, ry, fmaf(w.z, rz, pv[u] + w.w)));
            h0[o] = fmaxf(v, 0.0f);
        }
    }

    // layer 1, streamed out 4 outputs at a time (keeps register count low)
    float4* hout = (float4*)(g_H1 + (size_t)row * 64);
#pragma unroll 1
    for (int o4 = 0; o4 < 16; o4++) {
        float a0 = B1F[o4 * 4 + 0], a1 = B1F[o4 * 4 + 1];
        float a2 = B1F[o4 * 4 + 2], a3 = B1F[o4 * 4 + 3];
        const float4* wr0 = (const float4*)(W1S + (o4 * 4 + 0) * 64);
        const float4* wr1 = (const float4*)(W1S + (o4 * 4 + 1) * 64);
        const float4* wr2 = (const float4*)(W1S + (o4 * 4 + 2) * 64);
        const float4* wr3 = (const float4*)(W1S + (o4 * 4 + 3) * 64);
#pragma unroll
        for (int c4 = 0; c4 < 16; c4++) {
            float4 x0 = wr0[c4], x1 = wr1[c4], x2 = wr2[c4], x3 = wr3[c4];
            float hA = h0[c4 * 4 + 0], hB = h0[c4 * 4 + 1];
            float hC = h0[c4 * 4 + 2], hD = h0[c4 * 4 + 3];
            a0 = fmaf(x0.x, hA, a0); a0 = fmaf(x0.y, hB, a0);
            a0 = fmaf(x0.z, hC, a0); a0 = fmaf(x0.w, hD, a0);
            a1 = fmaf(x1.x, hA, a1); a1 = fmaf(x1.y, hB, a1);
            a1 = fmaf(x1.z, hC, a1); a1 = fmaf(x1.w, hD, a1);
            a2 = fmaf(x2.x, hA, a2); a2 = fmaf(x2.y, hB, a2);
            a2 = fmaf(x2.z, hC, a2); a2 = fmaf(x2.w, hD, a2);
            a3 = fmaf(x3.x, hA, a3); a3 = fmaf(x3.y, hB, a3);
            a3 = fmaf(x3.z, hC, a3); a3 = fmaf(x3.w, hD, a3);
        }
        hout[o4] = make_float4(fmaxf(a0, 0.0f), fmaxf(a1, 0.0f),
                               fmaxf(a2, 0.0f), fmaxf(a3, 0.0f));
    }
}

// ---------------- kernel 4b: layer2 + maxpool ----------------
__global__ void __launch_bounds__(128) mlp2_kernel(
    const float* __restrict__ w2, const float* __restrict__ b2,
    const float* __restrict__ g2, const float* __restrict__ be2,
    const float* __restrict__ rm2, const float* __restrict__ rv2,
    float* __restrict__ out)
{
    __shared__ float W2S[8192];    // [o][c] folded
    __shared__ float B2F[128];
    __shared__ float S2[128];

    int tid = threadIdx.x;
    {
        float s2v = fold_scale(g2[tid], rv2[tid]);
        S2[tid]  = s2v;
        B2F[tid] = (b2[tid] - rm2[tid]) * s2v + be2[tid];
    }
    __syncthreads();
    for (int e = tid; e < 8192; e += 128) W2S[e] = w2[e] * S2[e >> 6];
    __syncthreads();

    int row  = blockIdx.x * 128 + tid;
    int q    = row >> 4;
    int lane = tid & 31;

    float h1[64];
    const float4* hin = (const float4*)(g_H1 + (size_t)row * 64);
#pragma unroll
    for (int c4 = 0; c4 < 16; c4++) {
        float4 h = hin[c4];
        h1[c4 * 4 + 0] = h.x; h1[c4 * 4 + 1] = h.y;
        h1[c4 * 4 + 2] = h.z; h1[c4 * 4 + 3] = h.w;
    }

    float* orow = out + (size_t)q * C2;
#pragma unroll 2
    for (int o = 0; o < C2; o++) {
        const float4* wr = (const float4*)(W2S + o * 64);
        float acc = B2F[o];
#pragma unroll
        for (int c4 = 0; c4 < 16; c4++) {
            float4 a = wr[c4];
            acc = fmaf(a.x, h1[c4 * 4 + 0], acc);
            acc = fmaf(a.y, h1[c4 * 4 + 1], acc);
            acc = fmaf(a.z, h1[c4 * 4 + 2], acc);
            acc = fmaf(a.w, h1[c4 * 4 + 3], acc);
        }
        float v = fmaxf(acc, 0.0f);
        v = fmaxf(v, __shfl_xor_sync(0xFFFFFFFFu, v, 1));
        v = fmaxf(v, __shfl_xor_sync(0xFFFFFFFFu, v, 2));
        v = fmaxf(v, __shfl_xor_sync(0xFFFFFFFFu, v, 4));
        v = fmaxf(v, __shfl_xor_sync(0xFFFFFFFFu, v, 8));
        if ((lane & 15) == 0) orow[o] = v;
    }
}

// ---------------- launch ----------------
extern "C" void kernel_launch(void* const* d_in, const int* in_sizes, int n_in,
                              void* d_out, int out_size) {
    (void)in_sizes; (void)n_in; (void)out_size;
    const float* xyz    = (const float*)d_in[0];
    const float* points = (const float*)d_in[1];
    const float* w0  = (const float*)d_in[2];
    const float* b0  = (const float*)d_in[3];
    const float* g0  = (const float*)d_in[4];
    const float* be0 = (const float*)d_in[5];
    const float* rm0 = (const float*)d_in[6];
    const float* rv0 = (const float*)d_in[7];
    const float* w1  = (const float*)d_in[8];
    const float* b1  = (const float*)d_in[9];
    const float* g1  = (const float*)d_in[10];
    const float* be1 = (const float*)d_in[11];
    const float* rm1 = (const float*)d_in[12];
    const float* rv1 = (const float*)d_in[13];
    const float* w2  = (const float*)d_in[14];
    const float* b2  = (const float*)d_in[15];
    const float* g2  = (const float*)d_in[16];
    const float* be2 = (const float*)d_in[17];
    const float* rm2 = (const float*)d_in[18];
    const float* rv2 = (const float*)d_in[19];
    float* out = (float*)d_out;

    pack_kernel<<<NQ / 256, 256>>>(xyz);
    p0_kernel<<<NQ / 64, 256>>>(points, w0, g0, rv0);
    knnA_kernel<<<dim3(NQ / 128, NSLICE), 128>>>();
    knnB_kernel<<<NQ / 128, 128>>>();
    mlp1_kernel<<<NROWS / 128, 128>>>(w0, b0, g0, be0, rm0, rv0,
                                      w1, b1, g1, be1, rm1, rv1);
    mlp2_kernel<<<NROWS / 128, 128>>>(w2, b2, g2, be2, rm2, rv2, out);
}

// round 8
// speedup vs baseline: 1.2996x; 1.2846x over previous
#include <cuda_runtime.h>
#include <math_constants.h>

#define BATCH  4
#define NPTS   4096
#define NQ     (BATCH * NPTS)   // 16384
#define KNN    16
#define NROWS  (NQ * KNN)       // 262144
#define C2     128
#define EPSBN  1e-5f

#define TAU_SLICES   8          // slices of 64 covering candidates [0,512)
#define TAU_SLICE_N  64
#define COL_SLICES   8          // collect slices of 512
#define COL_SLICE_N  512
#define COL_CAP      64         // per-(q,slice) buffer cap (mean ~16)

// ---------------- scratch (no device allocations allowed) ----------------
__device__ float4 g_pack[NQ];                         // {x, y, z, |x|^2}
__device__ int    g_idx[NROWS];                       // final neighbor indices
__device__ float  g_P0[NQ * 64];                      // W0_pts' . points[j]
__device__ float  g_sd[NQ * 128];                     // tau survivors [q][slot]
__device__ float  g_tau[NQ];                          // per-query threshold
__device__ float  g_cd[(size_t)NQ * COL_SLICES * COL_CAP];  // collected dists
__device__ int    g_ci[(size_t)NQ * COL_SLICES * COL_CAP];  // collected idx
__device__ int    g_cnt[NQ * COL_SLICES];             // collected counts
__device__ float  g_H1[(size_t)NROWS * 64];           // layer-1 activations

// ---------------- helpers ----------------
__device__ __forceinline__ float fold_scale(float g, float rv) {
    float v = rv + EPSBN;
    float r = rsqrtf(v);
    r = r * (1.5f - 0.5f * v * r * r);
    return g * r;
}

// replicate reference rounding: (sq_i + sq_j) + (-2*dot), dot as fma chain
__device__ __forceinline__ float dist2f(float qx, float qy, float qz, float qsq, float4 p) {
    float dot = fmaf(qz, p.z, fmaf(qy, p.y, __fmul_rn(qx, p.x)));
    return __fadd_rn(__fadd_rn(qsq, p.w), __fmul_rn(-2.0f, dot));
}

// value-only replace-max insert (top-16 smallest)
__device__ __forceinline__ void ins_v(float dd, float* d, float& wmax) {
    bool done = false;
#pragma unroll
    for (int i = 0; i < KNN; i++) {
        bool m = (!done) && (d[i] == wmax);
        if (m) d[i] = dd;
        done = done || m;
    }
    wmax = d[0];
#pragma unroll
    for (int i = 1; i < KNN; i++) wmax = fmaxf(wmax, d[i]);
}

// ---------------- kernel 1: pack xyz + squared norm ----------------
__global__ void pack_kernel(const float* __restrict__ xyz) {
    int i = blockIdx.x * blockDim.x + threadIdx.x;
    if (i < NQ) {
        float x = xyz[3 * i + 0];
        float y = xyz[3 * i + 1];
        float z = xyz[3 * i + 2];
        float sq = fmaf(z, z, fmaf(y, y, __fmul_rn(x, x)));
        g_pack[i] = make_float4(x, y, z, sq);
    }
}

// ---------------- kernel 2: P0[j][o] = sum_c W0'[o][3+c] * points[j][c] --------
__global__ void __launch_bounds__(256) p0_kernel(const float* __restrict__ points,
                                                 const float* __restrict__ w0,
                                                 const float* __restrict__ g0,
                                                 const float* __restrict__ rv0) {
    __shared__ float w0f[64][64];
    int tid = threadIdx.x;
    for (int e = tid; e < 4096; e += 256) {
        int o = e & 63, c = e >> 6;
        float s = fold_scale(g0[o], rv0[o]);
        w0f[c][o] = w0[o * 67 + 3 + c] * s;
    }
    __syncthreads();

    int o     = tid & 63;
    int jl    = tid >> 6;
    int jbase = blockIdx.x * 64;
#pragma unroll 1
    for (int t = 0; t < 16; t++) {
        int j = jbase + jl + (t << 2);
        const float4* prow = (const float4*)(points + (size_t)j * 64);
        float acc = 0.0f;
#pragma unroll
        for (int c4 = 0; c4 < 16; c4++) {
            float4 p = prow[c4];
            acc = fmaf(p.x, w0f[c4 * 4 + 0][o], acc);
            acc = fmaf(p.y, w0f[c4 * 4 + 1][o], acc);
            acc = fmaf(p.z, w0f[c4 * 4 + 2][o], acc);
            acc = fmaf(p.w, w0f[c4 * 4 + 3][o], acc);
        }
        g_P0[(size_t)j * 64 + o] = acc;
    }
}

// ---------------- kernel 3a: tauA — per-slice top-16 dists over cand [0,512) ----
// grid (NQ/128, 8), block 128. Thread (q,s) scans 64 candidates.
__global__ void __launch_bounds__(128) tauA_kernel() {
    int q = blockIdx.x * 128 + threadIdx.x;
    int s = blockIdx.y;
    int base  = (q >> 12) << 12;
    int cbase = base + s * TAU_SLICE_N;
    const float4* __restrict__ cand = g_pack + cbase;

    float4 me = g_pack[q];
    float qx = me.x, qy = me.y, qz = me.z, qsq = me.w;

    float d[KNN];
#pragma unroll
    for (int i = 0; i < KNN; i++) d[i] = CUDART_INF_F;
    float wmax = CUDART_INF_F;

    for (int c = 0; c < TAU_SLICE_N; c += 4) {
        float dd0 = dist2f(qx, qy, qz, qsq, cand[c + 0]);
        float dd1 = dist2f(qx, qy, qz, qsq, cand[c + 1]);
        float dd2 = dist2f(qx, qy, qz, qsq, cand[c + 2]);
        float dd3 = dist2f(qx, qy, qz, qsq, cand[c + 3]);
        if (dd0 < wmax) ins_v(dd0, d, wmax);
        if (dd1 < wmax) ins_v(dd1, d, wmax);
        if (dd2 < wmax) ins_v(dd2, d, wmax);
        if (dd3 < wmax) ins_v(dd3, d, wmax);
    }

#pragma unroll
    for (int i = 0; i < KNN; i++) g_sd[(size_t)q * 128 + s * KNN + i] = d[i];
}

// ---------------- kernel 3b: tauB — tau = 16th smallest of 128 survivors -------
// warp per query; lanes each hold 4 survivor distances.
__global__ void __launch_bounds__(128) tauB_kernel() {
    int lane = threadIdx.x & 31;
    int q = blockIdx.x * 4 + (threadIdx.x >> 5);

    float4 v4 = *(const float4*)(g_sd + (size_t)q * 128 + lane * 4);
    float v0 = v4.x, v1 = v4.y, v2 = v4.z, v3 = v4.w;

    float tau = CUDART_INF_F;
#pragma unroll
    for (int it = 0; it < KNN; it++) {
        float m = fminf(fminf(v0, v1), fminf(v2, v3));
#pragma unroll
        for (int off = 16; off; off >>= 1)
            m = fminf(m, __shfl_xor_sync(0xFFFFFFFFu, m, off));
        // remove all copies of m (duplicate removal only loosens tau -> safe)
        if (v0 == m) v0 = CUDART_INF_F;
        if (v1 == m) v1 = CUDART_INF_F;
        if (v2 == m) v2 = CUDART_INF_F;
        if (v3 == m) v3 = CUDART_INF_F;
        tau = m;
    }
    if (lane == 0) g_tau[q] = tau;
}

// ---------------- kernel 3c: collect — compact all candidates with d <= tau ----
// grid (NQ/128, 8), block 128. Thread (q,s) scans 512 candidates.
__global__ void __launch_bounds__(128) collect_kernel() {
    int q = blockIdx.x * 128 + threadIdx.x;
    int s = blockIdx.y;
    int base  = (q >> 12) << 12;
    int cbase = base + s * COL_SLICE_N;
    const float4* __restrict__ cand = g_pack + cbase;

    float4 me = g_pack[q];
    float qx = me.x, qy = me.y, qz = me.z, qsq = me.w;
    float tau = g_tau[q];

    size_t obase = ((size_t)q * COL_SLICES + s) * COL_CAP;
    int cnt = 0;

    for (int c = 0; c < COL_SLICE_N; c += 4) {
        float dd0 = dist2f(qx, qy, qz, qsq, cand[c + 0]);
        float dd1 = dist2f(qx, qy, qz, qsq, cand[c + 1]);
        float dd2 = dist2f(qx, qy, qz, qsq, cand[c + 2]);
        float dd3 = dist2f(qx, qy, qz, qsq, cand[c + 3]);
        if (dd0 <= tau && cnt < COL_CAP) { g_cd[obase + cnt] = dd0; g_ci[obase + cnt] = cbase + c + 0; cnt++; }
        if (dd1 <= tau && cnt < COL_CAP) { g_cd[obase + cnt] = dd1; g_ci[obase + cnt] = cbase + c + 1; cnt++; }
        if (dd2 <= tau && cnt < COL_CAP) { g_cd[obase + cnt] = dd2; g_ci[obase + cnt] = cbase + c + 2; cnt++; }
        if (dd3 <= tau && cnt < COL_CAP) { g_cd[obase + cnt] = dd3; g_ci[obase + cnt] = cbase + c + 3; cnt++; }
    }
    g_cnt[q * COL_SLICES + s] = cnt;
}

// ---------------- kernel 3d: select — exact top-16 of collected entries --------
// warp per query. 64-bit keys (monotone_dist<<32 | idx): lexicographic compare
// reproduces top_k's smallest-index tie-break; key-match removal is branchless.
__global__ void __launch_bounds__(128) select_kernel() {
    int lane = threadIdx.x & 31;
    int q = blockIdx.x * 4 + (threadIdx.x >> 5);

    int cnt = (lane < COL_SLICES) ? g_cnt[q * COL_SLICES + lane] : 0;
    int pre = cnt;
#pragma unroll
    for (int off = 1; off < 8; off <<= 1) {
        int n = __shfl_up_sync(0xFFFFFFFFu, pre, off);
        if (lane >= off) pre += n;
    }
    int p0 = __shfl_sync(0xFFFFFFFFu, pre, 0);
    int p1 = __shfl_sync(0xFFFFFFFFu, pre, 1);
    int p2 = __shfl_sync(0xFFFFFFFFu, pre, 2);
    int p3 = __shfl_sync(0xFFFFFFFFu, pre, 3);
    int p4 = __shfl_sync(0xFFFFFFFFu, pre, 4);
    int p5 = __shfl_sync(0xFFFFFFFFu, pre, 5);
    int p6 = __shfl_sync(0xFFFFFFFFu, pre, 6);
    int total = __shfl_sync(0xFFFFFFFFu, pre, 7);   // <= 512 by cap

    unsigned long long key[16];
#pragma unroll
    for (int g = 0; g < 16; g++) {
        key[g] = ~0ull;
        int e = lane + (g << 5);
        if (e < total) {
            int s = (e >= p0) + (e >= p1) + (e >= p2) + (e >= p3)
                  + (e >= p4) + (e >= p5) + (e >= p6);
            int start = 0;
            if (s > 0) start = p0;
            if (s > 1) start = p1;
            if (s > 2) start = p2;
            if (s > 3) start = p3;
            if (s > 4) start = p4;
            if (s > 5) start = p5;
            if (s > 6) start = p6;
            size_t off = ((size_t)q * COL_SLICES + s) * COL_CAP + (e - start);
            float d  = g_cd[off];
            int   ci = g_ci[off];
            unsigned u = __float_as_uint(d);
            u = ((int)u < 0) ? ~u : (u | 0x80000000u);
            key[g] = ((unsigned long long)u << 32) | (unsigned)ci;
        }
    }

#pragma unroll 1
    for (int it = 0; it < KNN; it++) {
        unsigned long long m = key[0];
#pragma unroll
        for (int i = 1; i < 16; i++) m = (key[i] < m) ? key[i] : m;
#pragma unroll
        for (int off = 16; off; off >>= 1) {
            unsigned long long o = __shfl_xor_sync(0xFFFFFFFFu, m, off);
            m = (o < m) ? o : m;
        }
#pragma unroll
        for (int i = 0; i < 16; i++)
            if (key[i] == m) key[i] = ~0ull;
        if (lane == 0) g_idx[q * KNN + it] = (int)(m & 0xFFFFFFFFu);
    }
}

// ---------------- kernel 4a: layer0 + layer1 -> g_H1 ----------------
__global__ void __launch_bounds__(128) mlp1_kernel(
    const float* __restrict__ w0, const float* __restrict__ b0,
    const float* __restrict__ g0, const float* __restrict__ be0,
    const float* __restrict__ rm0, const float* __restrict__ rv0,
    const float* __restrict__ w1, const float* __restrict__ b1,
    const float* __restrict__ g1, const float* __restrict__ be1,
    const float* __restrict__ rm1, const float* __restrict__ rv1)
{
    __shared__ float4 W0B[64];
    __shared__ float  W1S[4096];
    __shared__ float  B1F[64];
    __shared__ float  S1[64];

    int tid = threadIdx.x;
    if (tid < 64) {
        float s0 = fold_scale(g0[tid], rv0[tid]);
        W0B[tid] = make_float4(w0[tid * 67 + 0] * s0,
                               w0[tid * 67 + 1] * s0,
                               w0[tid * 67 + 2] * s0,
                               (b0[tid] - rm0[tid]) * s0 + be0[tid]);
        float s1v = fold_scale(g1[tid], rv1[tid]);
        S1[tid]  = s1v;
        B1F[tid] = (b1[tid] - rm1[tid]) * s1v + be1[tid];
    }
    __syncthreads();
    for (int e = tid; e < 4096; e += 128) W1S[e] = w1[e] * S1[e >> 6];
    __syncthreads();

    int row = blockIdx.x * 128 + tid;
    int q   = row >> 4;
    int j   = g_idx[row];

    float4 pj = g_pack[j];
    float4 pq = g_pack[q];
    float rx = pj.x - pq.x, ry = pj.y - pq.y, rz = pj.z - pq.z;

    float h0[64];
    const float4* p0row = (const float4*)(g_P0 + (size_t)j * 64);
#pragma unroll
    for (int o4 = 0; o4 < 16; o4++) {
        float4 p = p0row[o4];
        float pv[4] = { p.x, p.y, p.z, p.w };
#pragma unroll
        for (int u = 0; u < 4; u++) {
            int o = o4 * 4 + u;
            float4 w = W0B[o];
            float v = fmaf(w.x, rx, fmaf(w.y, ry, fmaf(w.z, rz, pv[u] + w.w)));
            h0[o] = fmaxf(v, 0.0f);
        }
    }

    float4* hout = (float4*)(g_H1 + (size_t)row * 64);
#pragma unroll 1
    for (int o4 = 0; o4 < 16; o4++) {
        float a0 = B1F[o4 * 4 + 0], a1 = B1F[o4 * 4 + 1];
        float a2 = B1F[o4 * 4 + 2], a3 = B1F[o4 * 4 + 3];
        const float4* wr0 = (const float4*)(W1S + (o4 * 4 + 0) * 64);
        const float4* wr1 = (const float4*)(W1S + (o4 * 4 + 1) * 64);
        const float4* wr2 = (const float4*)(W1S + (o4 * 4 + 2) * 64);
        const float4* wr3 = (const float4*)(W1S + (o4 * 4 + 3) * 64);
#pragma unroll
        for (int c4 = 0; c4 < 16; c4++) {
            float4 x0 = wr0[c4], x1 = wr1[c4], x2 = wr2[c4], x3 = wr3[c4];
            float hA = h0[c4 * 4 + 0], hB = h0[c4 * 4 + 1];
            float hC = h0[c4 * 4 + 2], hD = h0[c4 * 4 + 3];
            a0 = fmaf(x0.x, hA, a0); a0 = fmaf(x0.y, hB, a0);
            a0 = fmaf(x0.z, hC, a0); a0 = fmaf(x0.w, hD, a0);
            a1 = fmaf(x1.x, hA, a1); a1 = fmaf(x1.y, hB, a1);
            a1 = fmaf(x1.z, hC, a1); a1 = fmaf(x1.w, hD, a1);
            a2 = fmaf(x2.x, hA, a2); a2 = fmaf(x2.y, hB, a2);
            a2 = fmaf(x2.z, hC, a2); a2 = fmaf(x2.w, hD, a2);
            a3 = fmaf(x3.x, hA, a3); a3 = fmaf(x3.y, hB, a3);
            a3 = fmaf(x3.z, hC, a3); a3 = fmaf(x3.w, hD, a3);
        }
        hout[o4] = make_float4(fmaxf(a0, 0.0f), fmaxf(a1, 0.0f),
                               fmaxf(a2, 0.0f), fmaxf(a3, 0.0f));
    }
}

// ---------------- kernel 4b: layer2 + maxpool ----------------
__global__ void __launch_bounds__(128) mlp2_kernel(
    const float* __restrict__ w2, const float* __restrict__ b2,
    const float* __restrict__ g2, const float* __restrict__ be2,
    const float* __restrict__ rm2, const float* __restrict__ rv2,
    float* __restrict__ out)
{
    __shared__ float W2S[8192];
    __shared__ float B2F[128];
    __shared__ float S2[128];

    int tid = threadIdx.x;
    {
        float s2v = fold_scale(g2[tid], rv2[tid]);
        S2[tid]  = s2v;
        B2F[tid] = (b2[tid] - rm2[tid]) * s2v + be2[tid];
    }
    __syncthreads();
    for (int e = tid; e < 8192; e += 128) W2S[e] = w2[e] * S2[e >> 6];
    __syncthreads();

    int row  = blockIdx.x * 128 + tid;
    int q    = row >> 4;
    int lane = tid & 31;

    float h1[64];
    const float4* hin = (const float4*)(g_H1 + (size_t)row * 64);
#pragma unroll
    for (int c4 = 0; c4 < 16; c4++) {
        float4 h = hin[c4];
        h1[c4 * 4 + 0] = h.x; h1[c4 * 4 + 1] = h.y;
        h1[c4 * 4 + 2] = h.z; h1[c4 * 4 + 3] = h.w;
    }

    float* orow = out + (size_t)q * C2;
#pragma unroll 2
    for (int o = 0; o < C2; o++) {
        const float4* wr = (const float4*)(W2S + o * 64);
        float acc = B2F[o];
#pragma unroll
        for (int c4 = 0; c4 < 16; c4++) {
            float4 a = wr[c4];
            acc = fmaf(a.x, h1[c4 * 4 + 0], acc);
            acc = fmaf(a.y, h1[c4 * 4 + 1], acc);
            acc = fmaf(a.z, h1[c4 * 4 + 2], acc);
            acc = fmaf(a.w, h1[c4 * 4 + 3], acc);
        }
        float v = fmaxf(acc, 0.0f);
        v = fmaxf(v, __shfl_xor_sync(0xFFFFFFFFu, v, 1));
        v = fmaxf(v, __shfl_xor_sync(0xFFFFFFFFu, v, 2));
        v = fmaxf(v, __shfl_xor_sync(0xFFFFFFFFu, v, 4));
        v = fmaxf(v, __shfl_xor_sync(0xFFFFFFFFu, v, 8));
        if ((lane & 15) == 0) orow[o] = v;
    }
}

// ---------------- launch ----------------
extern "C" void kernel_launch(void* const* d_in, const int* in_sizes, int n_in,
                              void* d_out, int out_size) {
    (void)in_sizes; (void)n_in; (void)out_size;
    const float* xyz    = (const float*)d_in[0];
    const float* points = (const float*)d_in[1];
    const float* w0  = (const float*)d_in[2];
    const float* b0  = (const float*)d_in[3];
    const float* g0  = (const float*)d_in[4];
    const float* be0 = (const float*)d_in[5];
    const float* rm0 = (const float*)d_in[6];
    const float* rv0 = (const float*)d_in[7];
    const float* w1  = (const float*)d_in[8];
    const float* b1  = (const float*)d_in[9];
    const float* g1  = (const float*)d_in[10];
    const float* be1 = (const float*)d_in[11];
    const float* rm1 = (const float*)d_in[12];
    const float* rv1 = (const float*)d_in[13];
    const float* w2  = (const float*)d_in[14];
    const float* b2  = (const float*)d_in[15];
    const float* g2  = (const float*)d_in[16];
    const float* be2 = (const float*)d_in[17];
    const float* rm2 = (const float*)d_in[18];
    const float* rv2 = (const float*)d_in[19];
    float* out = (float*)d_out;

    pack_kernel<<<NQ / 256, 256>>>(xyz);
    p0_kernel<<<NQ / 64, 256>>>(points, w0, g0, rv0);
    tauA_kernel<<<dim3(NQ / 128, TAU_SLICES), 128>>>();
    tauB_kernel<<<NQ / 4, 128>>>();
    collect_kernel<<<dim3(NQ / 128, COL_SLICES), 128>>>();
    select_kernel<<<NQ / 4, 128>>>();
    mlp1_kernel<<<NROWS / 128, 128>>>(w0, b0, g0, be0, rm0, rv0,
                                      w1, b1, g1, be1, rm1, rv1);
    mlp2_kernel<<<NROWS / 128, 128>>>(w2, b2, g2, be2, rm2, rv2, out);
}